// round 11
// baseline (speedup 1.0000x reference)
#include <cuda_runtime.h>
#include <cuda_fp16.h>
#include <cstdint>

#define NN 2048
#define EMBD 16
#define BB 64
#define CC 64

// Scratch (no cudaMalloc allowed)
static __device__ __half g_A[NN * NN];            // adjacency, fp16
static __device__ __half g_xh[BB * NN * CC];      // fp16(x), [b][m][c]
static __device__ __half g_y1h[BB * NN * CC];     // A@X, fp16, [b][n][c]
static __device__ __half g_y2h[BB * NN * CC];     // 2A@y1 - X, fp16, [b][n][c]
static __device__ __half g_WT[NN * 3 * CC * CC];  // per-node weights [n][o][kk], fp16

// ---------------------------------------------------------------------------
__device__ __forceinline__ uint32_t smem_u32(const void* p) {
    uint32_t a;
    asm("{ .reg .u64 t; cvta.to.shared.u64 t, %1; cvt.u32.u64 %0, t; }" : "=r"(a) : "l"(p));
    return a;
}
__device__ __forceinline__ void cp16(uint32_t dst, const void* src) {
    asm volatile("cp.async.cg.shared.global [%0], [%1], 16;" :: "r"(dst), "l"(src));
}
__device__ __forceinline__ void cp_commit() { asm volatile("cp.async.commit_group;"); }
__device__ __forceinline__ void cp_wait1() { asm volatile("cp.async.wait_group 1;" ::: "memory"); }
__device__ __forceinline__ void cp_wait0() { asm volatile("cp.async.wait_group 0;" ::: "memory"); }

__device__ __forceinline__ void mma16(float* d, const uint32_t* a, uint32_t b0, uint32_t b1) {
    asm volatile(
        "mma.sync.aligned.m16n8k16.row.col.f32.f16.f16.f32 "
        "{%0,%1,%2,%3}, {%4,%5,%6,%7}, {%8,%9}, {%0,%1,%2,%3};"
        : "+f"(d[0]), "+f"(d[1]), "+f"(d[2]), "+f"(d[3])
        : "r"(a[0]), "r"(a[1]), "r"(a[2]), "r"(a[3]), "r"(b0), "r"(b1));
}
__device__ __forceinline__ void ldsm4(uint32_t* r, uint32_t addr) {
    asm volatile("ldmatrix.sync.aligned.m8n8.x4.shared.b16 {%0,%1,%2,%3}, [%4];"
                 : "=r"(r[0]), "=r"(r[1]), "=r"(r[2]), "=r"(r[3]) : "r"(addr));
}
__device__ __forceinline__ void ldsm4t(uint32_t* r, uint32_t addr) {
    asm volatile("ldmatrix.sync.aligned.m8n8.x4.trans.shared.b16 {%0,%1,%2,%3}, [%4];"
                 : "=r"(r[0]), "=r"(r[1]), "=r"(r[2]), "=r"(r[3]) : "r"(addr));
}

// ---------------------------------------------------------------------------
// prep_kernel: fused supports + xh-convert + wpre. Heterogeneous dispatch:
//   bid [0, 512):        supports, 4 rows per block
//   bid [512, 4608):     xh convert, 16 elems/thread
//   bid [4608, 7680):    wpre, (kx = w%48, ny = w/48)
// All share a 32KB dynamic smem arena.
// ---------------------------------------------------------------------------
#define SR 4
#define PREP_SMEM 32768
#define XH_BLOCKS ((BB * NN * CC) / (256 * 16))   // 2048

__global__ __launch_bounds__(256) void prep_kernel(const float* __restrict__ E,
                                                   const float* __restrict__ X,
                                                   const float* __restrict__ wp,
                                                   __half* __restrict__ A,
                                                   __half* __restrict__ XH,
                                                   __half* __restrict__ WT) {
    extern __shared__ char dyn[];
    int bid = blockIdx.x;
    int tid = threadIdx.x;

    if (bid < 512) {
        // ---------------- supports ----------------
        float* zs = reinterpret_cast<float*>(dyn);   // SR * NN
        __shared__ float red[SR][8];
        __shared__ float en[SR][EMBD];
        int row0 = bid * SR;
        if (tid < SR * EMBD) en[tid >> 4][tid & 15] = E[row0 * EMBD + tid];
        __syncthreads();

        float er[SR][EMBD];
#pragma unroll
        for (int r = 0; r < SR; r++)
#pragma unroll
            for (int d = 0; d < EMBD; d++) er[r][d] = en[r][d];

        float lsum[SR] = {0.f, 0.f, 0.f, 0.f};
        for (int j = tid; j < NN; j += 256) {
            const float4* ej = reinterpret_cast<const float4*>(E + (size_t)j * EMBD);
            float4 v0 = ej[0], v1 = ej[1], v2 = ej[2], v3 = ej[3];
#pragma unroll
            for (int r = 0; r < SR; r++) {
                float s = 0.f;
                s = fmaf(er[r][0], v0.x, s);  s = fmaf(er[r][1], v0.y, s);
                s = fmaf(er[r][2], v0.z, s);  s = fmaf(er[r][3], v0.w, s);
                s = fmaf(er[r][4], v1.x, s);  s = fmaf(er[r][5], v1.y, s);
                s = fmaf(er[r][6], v1.z, s);  s = fmaf(er[r][7], v1.w, s);
                s = fmaf(er[r][8], v2.x, s);  s = fmaf(er[r][9], v2.y, s);
                s = fmaf(er[r][10], v2.z, s); s = fmaf(er[r][11], v2.w, s);
                s = fmaf(er[r][12], v3.x, s); s = fmaf(er[r][13], v3.y, s);
                s = fmaf(er[r][14], v3.z, s); s = fmaf(er[r][15], v3.w, s);
                float e = __expf(fmaxf(s, 0.f));
                zs[r * NN + j] = e;
                lsum[r] += e;
            }
        }
#pragma unroll
        for (int r = 0; r < SR; r++) {
#pragma unroll
            for (int o = 16; o > 0; o >>= 1) lsum[r] += __shfl_xor_sync(~0u, lsum[r], o);
            if ((tid & 31) == 0) red[r][tid >> 5] = lsum[r];
        }
        __syncthreads();
        float inv[SR];
#pragma unroll
        for (int r = 0; r < SR; r++) {
            float s = 0.f;
#pragma unroll
            for (int w = 0; w < 8; w++) s += red[r][w];
            inv[r] = 1.f / s;
        }
        for (int j = tid; j < NN; j += 256) {
#pragma unroll
            for (int r = 0; r < SR; r++)
                A[(size_t)(row0 + r) * NN + j] = __float2half_rn(zs[r * NN + j] * inv[r]);
        }
    } else if (bid < 512 + XH_BLOCKS) {
        // ---------------- xh convert (16 elems/thread) ----------------
        size_t base = ((size_t)(bid - 512) * 256 + tid) * 16;
#pragma unroll
        for (int h = 0; h < 2; h++) {
            size_t i = base + h * 8;
            float4 a = *reinterpret_cast<const float4*>(X + i);
            float4 b = *reinterpret_cast<const float4*>(X + i + 4);
            union { uint4 u; __half2 hh[4]; } o;
            o.hh[0] = __floats2half2_rn(a.x, a.y);
            o.hh[1] = __floats2half2_rn(a.z, a.w);
            o.hh[2] = __floats2half2_rn(b.x, b.y);
            o.hh[3] = __floats2half2_rn(b.z, b.w);
            *reinterpret_cast<uint4*>(XH + i) = o.u;
        }
    } else {
        // ---------------- wpre ----------------
        float* wps = reinterpret_cast<float*>(dyn);              // [16][256]
        float* Es = reinterpret_cast<float*>(dyn + 16384);       // [32][16]
        int w = bid - (512 + XH_BLOCKS);
        int bx = w % 48;
        int ny = w / 48;
        int k0 = bx * 4;
        int idx0 = bx * 256;
        int n0 = ny * 32;
#pragma unroll
        for (int i = 0; i < 4; i++) {
            int f = tid + i * 256;
            int d = f >> 6, c4 = f & 63;
            float4 v = *reinterpret_cast<const float4*>(wp + (size_t)d * 12288 + idx0 + c4 * 4);
            *reinterpret_cast<float4*>(&wps[d * 256 + c4 * 4]) = v;
        }
        if (tid < 128) {
            int nl = tid >> 2, dq = tid & 3;
            float4 v = *reinterpret_cast<const float4*>(E + (n0 + nl) * EMBD + dq * 4);
            *reinterpret_cast<float4*>(&Es[nl * EMBD + dq * 4]) = v;
        }
        __syncthreads();

        int o = tid & 63;
        int g = tid >> 6;
        float wc[4][EMBD];
#pragma unroll
        for (int dk = 0; dk < 4; dk++)
#pragma unroll
            for (int d = 0; d < EMBD; d++) wc[dk][d] = wps[d * 256 + dk * 64 + o];

#pragma unroll
        for (int q = 0; q < 8; q++) {
            int nl = g * 8 + q;
            float s[4] = {0.f, 0.f, 0.f, 0.f};
#pragma unroll
            for (int d = 0; d < EMBD; d++) {
                float e = Es[nl * EMBD + d];
#pragma unroll
                for (int dk = 0; dk < 4; dk++) s[dk] = fmaf(e, wc[dk][d], s[dk]);
            }
            __half2 h01 = __halves2half2(__float2half_rn(s[0]), __float2half_rn(s[1]));
            __half2 h23 = __halves2half2(__float2half_rn(s[2]), __float2half_rn(s[3]));
            __half2* dst = reinterpret_cast<__half2*>(
                WT + (size_t)(n0 + nl) * 12288 + o * 192 + k0);
            dst[0] = h01;
            dst[1] = h23;
        }
    }
}

// ---------------------------------------------------------------------------
// fp16 mma.sync GEMM, B row-major via ldmatrix.trans, K=64 stages.
// CTA 128x128xK64, 8 warps (2m x 4n), warp tile 64x32, 3-stage cp.async.
// mode 1: Yh = acc.  mode 2: Yh = 2*acc - Xh.
// ---------------------------------------------------------------------------
#define GEMM_SMEM 98304  // 3 stages x 32KB

__global__ __launch_bounds__(256, 2) void mma_gemm(const __half* __restrict__ Ag,
                                                   const __half* __restrict__ Bh,
                                                   __half* __restrict__ Yh,
                                                   const __half* __restrict__ Xh,
                                                   int mode) {
    extern __shared__ char smc[];
    uint32_t sb = smem_u32(smc);

    int tid = threadIdx.x;
    int wid = tid >> 5;
    int lid = tid & 31;
    int wm = wid & 1;
    int wn = wid >> 1;
    int n0 = blockIdx.x * 128;
    int bc0 = blockIdx.y * 128;
    int b0 = bc0 >> 6;

    const __half* Arow = Ag + (size_t)n0 * NN;

    auto load_tile = [&](int it, int buf) {
        int m0 = it * 64;
        uint32_t ab = sb + buf * 32768;
        uint32_t bb = ab + 16384;
#pragma unroll
        for (int i = 0; i < 4; i++) {
            int idx = tid + i * 256;
            int row = idx >> 3, c = idx & 7;
            int pc = c ^ (row & 7);
            cp16(ab + row * 128 + pc * 16, Arow + (size_t)row * NN + m0 + c * 8);
        }
#pragma unroll
        for (int i = 0; i < 4; i++) {
            int idx = tid + i * 256;
            int row = idx >> 3, c = idx & 7;
            int bloc = row >> 6, m = row & 63;
            int pc = c ^ (m & 7);
            cp16(bb + row * 128 + pc * 16,
                 Bh + ((size_t)(b0 + bloc) * NN + m0 + m) * CC + c * 8);
        }
        cp_commit();
    };

    int g = lid >> 3, lrw = lid & 7;
    int chHalf = g >> 1;
    uint32_t aBase = (uint32_t)(wm * 64 + (g & 1) * 8 + lrw) * 128;
    int bloc_w = wn >> 1;
    int warp_c = (wn & 1) * 32;
    uint32_t bRowRel = (uint32_t)(bloc_w * 64 + (g & 1) * 8 + lrw) * 128;
    int chunk0 = (warp_c >> 3) + chHalf;
    uint32_t bSw0 = (uint32_t)((chunk0 + 0) ^ lrw) * 16;
    uint32_t bSw1 = (uint32_t)((chunk0 + 2) ^ lrw) * 16;

    float acc[4][4][4];
#pragma unroll
    for (int mt = 0; mt < 4; mt++)
#pragma unroll
        for (int nt = 0; nt < 4; nt++)
#pragma unroll
            for (int q = 0; q < 4; q++) acc[mt][nt][q] = 0.f;

    load_tile(0, 0);
    load_tile(1, 1);

    const int ITERS = NN / 64;
    for (int it = 0; it < ITERS; it++) {
        int buf = it % 3;
        if (it == ITERS - 1) cp_wait0(); else cp_wait1();
        __syncthreads();
        uint32_t aB = sb + buf * 32768 + aBase;
        uint32_t bB = sb + buf * 32768 + 16384 + bRowRel;

#pragma unroll
        for (int ks = 0; ks < 4; ks++) {
            uint32_t af[4][4], bf[2][4];
            uint32_t apc = (uint32_t)((ks * 2 + chHalf) ^ lrw) * 16;
#pragma unroll
            for (int mt = 0; mt < 4; mt++) ldsm4(af[mt], aB + mt * 2048 + apc);
            uint32_t bko = (uint32_t)ks * 2048;
            ldsm4t(bf[0], bB + bko + bSw0);
            ldsm4t(bf[1], bB + bko + bSw1);
            if (ks == 0) {
                if (it + 2 < ITERS) load_tile(it + 2, (it + 2) % 3);
                else cp_commit();
            }
#pragma unroll
            for (int mt = 0; mt < 4; mt++) {
                mma16(acc[mt][0], af[mt], bf[0][0], bf[0][1]);
                mma16(acc[mt][1], af[mt], bf[0][2], bf[0][3]);
                mma16(acc[mt][2], af[mt], bf[1][0], bf[1][1]);
                mma16(acc[mt][3], af[mt], bf[1][2], bf[1][3]);
            }
        }
    }

    int lr = lid >> 2, lc = lid & 3;
#pragma unroll
    for (int mt = 0; mt < 4; mt++) {
#pragma unroll
        for (int nt = 0; nt < 4; nt++) {
            int n = n0 + wm * 64 + mt * 16 + lr;
            int bc = bc0 + wn * 32 + (nt >> 1) * 16 + (nt & 1) * 8 + lc * 2;
            int b = bc >> 6, c = bc & 63;
            float2 v0 = make_float2(acc[mt][nt][0], acc[mt][nt][1]);
            float2 v1 = make_float2(acc[mt][nt][2], acc[mt][nt][3]);
            if (mode == 2) {
                __half2 xh0 = *reinterpret_cast<const __half2*>(
                    Xh + ((size_t)b * NN + n) * CC + c);
                __half2 xh1 = *reinterpret_cast<const __half2*>(
                    Xh + ((size_t)b * NN + n + 8) * CC + c);
                float2 x0 = __half22float2(xh0);
                float2 x1 = __half22float2(xh1);
                v0.x = fmaf(2.f, v0.x, -x0.x);
                v0.y = fmaf(2.f, v0.y, -x0.y);
                v1.x = fmaf(2.f, v1.x, -x1.x);
                v1.y = fmaf(2.f, v1.y, -x1.y);
            }
            *reinterpret_cast<__half2*>(Yh + ((size_t)b * NN + n) * CC + c) =
                __floats2half2_rn(v0.x, v0.y);
            *reinterpret_cast<__half2*>(Yh + ((size_t)b * NN + n + 8) * CC + c) =
                __floats2half2_rn(v1.x, v1.y);
        }
    }
}

// ---------------------------------------------------------------------------
// out4: per-node fp16 tensor-core contraction. One block (128 thr, 4 warps) per n.
// ---------------------------------------------------------------------------
#define HSTR 200
#define OUT4_SMEM ((64 * HSTR * 2) * 2 + 64 * 4)
__global__ __launch_bounds__(128) void out4_kernel(const float* __restrict__ E,
                                                   const __half* __restrict__ WTg,
                                                   const float* __restrict__ bp,
                                                   float* __restrict__ OUT) {
    extern __shared__ char smc[];
    __half* XGs = reinterpret_cast<__half*>(smc);
    __half* WTs = XGs + 64 * HSTR;
    float* bs = reinterpret_cast<float*>(smc + 64 * HSTR * 2 * 2);
    __shared__ float en[EMBD];

    int n = blockIdx.x;
    int tid = threadIdx.x;
    int wid = tid >> 5;
    int lid = tid & 31;
    uint32_t xg_s = smem_u32(XGs);
    uint32_t wt_s = smem_u32(WTs);

    const __half* srcs[3] = {g_xh, g_y1h, g_y2h};
#pragma unroll
    for (int k = 0; k < 3; k++) {
        const __half* src = srcs[k];
#pragma unroll
        for (int rep = 0; rep < 4; rep++) {
            int c8 = tid + rep * 128;
            int b = c8 >> 3, i8 = c8 & 7;
            cp16(xg_s + (uint32_t)(b * HSTR + k * 64 + i8 * 8) * 2,
                 src + ((size_t)b * NN + n) * CC + i8 * 8);
        }
    }
    {
        const __half* src = WTg + (size_t)n * 12288;
#pragma unroll
        for (int rep = 0; rep < 12; rep++) {
            int c8 = tid + rep * 128;
            int idx = c8 * 8;
            int o = idx / 192, kk = idx - o * 192;
            cp16(wt_s + (uint32_t)(o * HSTR + kk) * 2, src + idx);
        }
    }
    cp_commit();

    if (tid < EMBD) en[tid] = E[n * EMBD + tid];
    __syncthreads();
    if (tid < 64) {
        float s = 0.f;
#pragma unroll
        for (int d = 0; d < EMBD; d++) s = fmaf(en[d], bp[d * 64 + tid], s);
        bs[tid] = s;
    }
    cp_wait0();
    __syncthreads();

    int lm = lid >> 3, lrw = lid & 7;
    uint32_t aLane = xg_s + (uint32_t)(wid * 16 + (lm & 1) * 8 + lrw) * (HSTR * 2) +
                     (lm >> 1) * 16;
    uint32_t bLane = wt_s + (uint32_t)((lm & 1) * 8 + lrw) * (HSTR * 2) +
                     (lm >> 1) * 16;

    float acc[8][4];
#pragma unroll
    for (int nt = 0; nt < 8; nt++)
#pragma unroll
        for (int q = 0; q < 4; q++) acc[nt][q] = 0.f;

#pragma unroll
    for (int kt = 0; kt < 12; kt++) {
        uint32_t koff = (uint32_t)kt * 32;
        uint32_t af[4];
        ldsm4(af, aLane + koff);
#pragma unroll
        for (int g = 0; g < 4; g++) {
            uint32_t bf[4];
            ldsm4(bf, bLane + g * 16 * (HSTR * 2) + koff);
            mma16(acc[g * 2 + 0], af, bf[0], bf[2]);
            mma16(acc[g * 2 + 1], af, bf[1], bf[3]);
        }
    }

    int lr = lid >> 2, lc = lid & 3;
    int b0 = wid * 16 + lr;
#pragma unroll
    for (int nt = 0; nt < 8; nt++) {
        int o = nt * 8 + lc * 2;
        float2 bias = *reinterpret_cast<const float2*>(&bs[o]);
        float2 v0 = make_float2(acc[nt][0] + bias.x, acc[nt][1] + bias.y);
        float2 v1 = make_float2(acc[nt][2] + bias.x, acc[nt][3] + bias.y);
        *reinterpret_cast<float2*>(OUT + ((size_t)b0 * NN + n) * CC + o) = v0;
        *reinterpret_cast<float2*>(OUT + ((size_t)(b0 + 8) * NN + n) * CC + o) = v1;
    }
}

// ---------------------------------------------------------------------------
extern "C" void kernel_launch(void* const* d_in, const int* in_sizes, int n_in,
                              void* d_out, int out_size) {
    const float *x = nullptr, *E = nullptr, *wp = nullptr, *bp = nullptr;
    for (int i = 0; i < n_in; i++) {
        switch (in_sizes[i]) {
            case BB * NN * CC:       x = (const float*)d_in[i]; break;
            case NN * EMBD:          E = (const float*)d_in[i]; break;
            case EMBD * 3 * CC * CC: wp = (const float*)d_in[i]; break;
            case EMBD * CC:          bp = (const float*)d_in[i]; break;
        }
    }
    float* out = (float*)d_out;

    __half *A, *xh, *y1h, *y2h, *WT;
    cudaGetSymbolAddress((void**)&A, g_A);
    cudaGetSymbolAddress((void**)&xh, g_xh);
    cudaGetSymbolAddress((void**)&y1h, g_y1h);
    cudaGetSymbolAddress((void**)&y2h, g_y2h);
    cudaGetSymbolAddress((void**)&WT, g_WT);

    cudaFuncSetAttribute(prep_kernel, cudaFuncAttributeMaxDynamicSharedMemorySize, PREP_SMEM);
    prep_kernel<<<512 + XH_BLOCKS + 3072, 256, PREP_SMEM>>>(E, x, wp, A, xh, WT);

    cudaFuncSetAttribute(mma_gemm, cudaFuncAttributeMaxDynamicSharedMemorySize, GEMM_SMEM);
    dim3 ggrid(NN / 128, (BB * CC) / 128);
    mma_gemm<<<ggrid, 256, GEMM_SMEM>>>(A, xh, y1h, nullptr, 1);
    mma_gemm<<<ggrid, 256, GEMM_SMEM>>>(A, y1h, y2h, xh, 2);

    cudaFuncSetAttribute(out4_kernel, cudaFuncAttributeMaxDynamicSharedMemorySize, OUT4_SMEM);
    out4_kernel<<<NN, 128, OUT4_SMEM>>>(E, WT, bp, out);
}

// round 12
// speedup vs baseline: 1.0060x; 1.0060x over previous
#include <cuda_runtime.h>
#include <cuda_fp16.h>
#include <cstdint>

#define NN 2048
#define EMBD 16
#define BB 64
#define CC 64

// Scratch (no cudaMalloc allowed)
static __device__ __half g_A[NN * NN];            // adjacency, fp16
static __device__ __half g_xh[BB * NN * CC];      // fp16(x), [b][m][c]
static __device__ __half g_y1h[BB * NN * CC];     // A@X, fp16, [b][n][c]
static __device__ __half g_y2h[BB * NN * CC];     // 2A@y1 - X, fp16, [b][n][c]
static __device__ __half g_WT[NN * 3 * CC * CC];  // per-node weights [n][o][kk], fp16

// ---------------------------------------------------------------------------
__device__ __forceinline__ uint32_t smem_u32(const void* p) {
    uint32_t a;
    asm("{ .reg .u64 t; cvta.to.shared.u64 t, %1; cvt.u32.u64 %0, t; }" : "=r"(a) : "l"(p));
    return a;
}
__device__ __forceinline__ void cp16(uint32_t dst, const void* src) {
    asm volatile("cp.async.cg.shared.global [%0], [%1], 16;" :: "r"(dst), "l"(src));
}
__device__ __forceinline__ void cp_commit() { asm volatile("cp.async.commit_group;"); }
__device__ __forceinline__ void cp_wait1() { asm volatile("cp.async.wait_group 1;" ::: "memory"); }
__device__ __forceinline__ void cp_wait0() { asm volatile("cp.async.wait_group 0;" ::: "memory"); }

__device__ __forceinline__ void mma16(float* d, const uint32_t* a, uint32_t b0, uint32_t b1) {
    asm volatile(
        "mma.sync.aligned.m16n8k16.row.col.f32.f16.f16.f32 "
        "{%0,%1,%2,%3}, {%4,%5,%6,%7}, {%8,%9}, {%0,%1,%2,%3};"
        : "+f"(d[0]), "+f"(d[1]), "+f"(d[2]), "+f"(d[3])
        : "r"(a[0]), "r"(a[1]), "r"(a[2]), "r"(a[3]), "r"(b0), "r"(b1));
}
__device__ __forceinline__ void ldsm4(uint32_t* r, uint32_t addr) {
    asm volatile("ldmatrix.sync.aligned.m8n8.x4.shared.b16 {%0,%1,%2,%3}, [%4];"
                 : "=r"(r[0]), "=r"(r[1]), "=r"(r[2]), "=r"(r[3]) : "r"(addr));
}
__device__ __forceinline__ void ldsm4t(uint32_t* r, uint32_t addr) {
    asm volatile("ldmatrix.sync.aligned.m8n8.x4.trans.shared.b16 {%0,%1,%2,%3}, [%4];"
                 : "=r"(r[0]), "=r"(r[1]), "=r"(r[2]), "=r"(r[3]) : "r"(addr));
}

// ---------------------------------------------------------------------------
// K0: A[r,:] = fp16(softmax(relu(E[r] . E[j]))), 4 rows per block.
// ---------------------------------------------------------------------------
#define SR 4
__global__ __launch_bounds__(256) void supports_kernel(const float* __restrict__ E,
                                                       __half* __restrict__ A) {
    extern __shared__ float zs[];               // SR * NN
    __shared__ float red[SR][8];
    __shared__ float en[SR][EMBD];
    int row0 = blockIdx.x * SR;
    int tid = threadIdx.x;
    if (tid < SR * EMBD) en[tid >> 4][tid & 15] = E[row0 * EMBD + tid];
    __syncthreads();

    float er[SR][EMBD];
#pragma unroll
    for (int r = 0; r < SR; r++)
#pragma unroll
        for (int d = 0; d < EMBD; d++) er[r][d] = en[r][d];

    float lsum[SR] = {0.f, 0.f, 0.f, 0.f};
    for (int j = tid; j < NN; j += 256) {
        const float4* ej = reinterpret_cast<const float4*>(E + (size_t)j * EMBD);
        float4 v0 = ej[0], v1 = ej[1], v2 = ej[2], v3 = ej[3];
#pragma unroll
        for (int r = 0; r < SR; r++) {
            float s = 0.f;
            s = fmaf(er[r][0], v0.x, s);  s = fmaf(er[r][1], v0.y, s);
            s = fmaf(er[r][2], v0.z, s);  s = fmaf(er[r][3], v0.w, s);
            s = fmaf(er[r][4], v1.x, s);  s = fmaf(er[r][5], v1.y, s);
            s = fmaf(er[r][6], v1.z, s);  s = fmaf(er[r][7], v1.w, s);
            s = fmaf(er[r][8], v2.x, s);  s = fmaf(er[r][9], v2.y, s);
            s = fmaf(er[r][10], v2.z, s); s = fmaf(er[r][11], v2.w, s);
            s = fmaf(er[r][12], v3.x, s); s = fmaf(er[r][13], v3.y, s);
            s = fmaf(er[r][14], v3.z, s); s = fmaf(er[r][15], v3.w, s);
            float e = __expf(fmaxf(s, 0.f));
            zs[r * NN + j] = e;
            lsum[r] += e;
        }
    }
#pragma unroll
    for (int r = 0; r < SR; r++) {
#pragma unroll
        for (int o = 16; o > 0; o >>= 1) lsum[r] += __shfl_xor_sync(~0u, lsum[r], o);
        if ((tid & 31) == 0) red[r][tid >> 5] = lsum[r];
    }
    __syncthreads();
    float inv[SR];
#pragma unroll
    for (int r = 0; r < SR; r++) {
        float s = 0.f;
#pragma unroll
        for (int w = 0; w < 8; w++) s += red[r][w];
        inv[r] = 1.f / s;
    }
    for (int j = tid; j < NN; j += 256) {
#pragma unroll
        for (int r = 0; r < SR; r++)
            A[(size_t)(row0 + r) * NN + j] = __float2half_rn(zs[r * NN + j] * inv[r]);
    }
}

// ---------------------------------------------------------------------------
// xh: fp16 convert of x (same layout). 16 elems/thread.
// ---------------------------------------------------------------------------
__global__ __launch_bounds__(256) void xh_kernel(const float* __restrict__ X,
                                                 __half* __restrict__ D) {
    size_t base = ((size_t)blockIdx.x * 256 + threadIdx.x) * 16;
#pragma unroll
    for (int h = 0; h < 2; h++) {
        size_t i = base + h * 8;
        float4 a = *reinterpret_cast<const float4*>(X + i);
        float4 b = *reinterpret_cast<const float4*>(X + i + 4);
        union { uint4 u; __half2 hh[4]; } o;
        o.hh[0] = __floats2half2_rn(a.x, a.y);
        o.hh[1] = __floats2half2_rn(a.z, a.w);
        o.hh[2] = __floats2half2_rn(b.x, b.y);
        o.hh[3] = __floats2half2_rn(b.z, b.w);
        *reinterpret_cast<uint4*>(D + i) = o.u;
    }
}

// ---------------------------------------------------------------------------
// W precompute (transposed, fp16): WT[n][o*192 + kk] = fp16(sum_d E[n,d]*wp[d, kk*64+o])
// ---------------------------------------------------------------------------
__global__ __launch_bounds__(256) void wpre_kernel(const float* __restrict__ E,
                                                   const float* __restrict__ wp,
                                                   __half* __restrict__ WT) {
    __shared__ float wps[EMBD][256];
    __shared__ float Es[32][EMBD];
    int k0 = blockIdx.x * 4;
    int idx0 = blockIdx.x * 256;
    int n0 = blockIdx.y * 32;
    int tid = threadIdx.x;
#pragma unroll
    for (int i = 0; i < 4; i++) {
        int f = tid + i * 256;
        int d = f >> 6, c4 = f & 63;
        float4 v = *reinterpret_cast<const float4*>(wp + (size_t)d * 12288 + idx0 + c4 * 4);
        *reinterpret_cast<float4*>(&wps[d][c4 * 4]) = v;
    }
    if (tid < 128) {
        int nl = tid >> 2, dq = tid & 3;
        float4 v = *reinterpret_cast<const float4*>(E + (n0 + nl) * EMBD + dq * 4);
        *reinterpret_cast<float4*>(&Es[nl][dq * 4]) = v;
    }
    __syncthreads();

    int o = tid & 63;
    int g = tid >> 6;
    float wc[4][EMBD];
#pragma unroll
    for (int dk = 0; dk < 4; dk++)
#pragma unroll
        for (int d = 0; d < EMBD; d++) wc[dk][d] = wps[d][dk * 64 + o];

#pragma unroll
    for (int q = 0; q < 8; q++) {
        int nl = g * 8 + q;
        float s[4] = {0.f, 0.f, 0.f, 0.f};
#pragma unroll
        for (int d = 0; d < EMBD; d++) {
            float e = Es[nl][d];
#pragma unroll
            for (int dk = 0; dk < 4; dk++) s[dk] = fmaf(e, wc[dk][d], s[dk]);
        }
        __half2 h01 = __halves2half2(__float2half_rn(s[0]), __float2half_rn(s[1]));
        __half2 h23 = __halves2half2(__float2half_rn(s[2]), __float2half_rn(s[3]));
        __half2* dst = reinterpret_cast<__half2*>(
            WT + (size_t)(n0 + nl) * 12288 + o * 192 + k0);
        dst[0] = h01;
        dst[1] = h23;
    }
}

// ---------------------------------------------------------------------------
// fp16 mma.sync GEMM, B row-major via ldmatrix.trans, K=64 stages.
// CTA 128x128xK64, 8 warps (2m x 4n), warp tile 64x32, 3-stage cp.async.
// mode 1: Yh = acc.  mode 2: Yh = 2*acc - Xh.
// ---------------------------------------------------------------------------
#define GEMM_SMEM 98304  // 3 stages x 32KB

__global__ __launch_bounds__(256, 2) void mma_gemm(const __half* __restrict__ Ag,
                                                   const __half* __restrict__ Bh,
                                                   __half* __restrict__ Yh,
                                                   const __half* __restrict__ Xh,
                                                   int mode) {
    extern __shared__ char smc[];
    uint32_t sb = smem_u32(smc);

    int tid = threadIdx.x;
    int wid = tid >> 5;
    int lid = tid & 31;
    int wm = wid & 1;
    int wn = wid >> 1;
    int n0 = blockIdx.x * 128;
    int bc0 = blockIdx.y * 128;
    int b0 = bc0 >> 6;

    const __half* Arow = Ag + (size_t)n0 * NN;

    auto load_tile = [&](int it, int buf) {
        int m0 = it * 64;
        uint32_t ab = sb + buf * 32768;
        uint32_t bb = ab + 16384;
#pragma unroll
        for (int i = 0; i < 4; i++) {
            int idx = tid + i * 256;
            int row = idx >> 3, c = idx & 7;
            int pc = c ^ (row & 7);
            cp16(ab + row * 128 + pc * 16, Arow + (size_t)row * NN + m0 + c * 8);
        }
#pragma unroll
        for (int i = 0; i < 4; i++) {
            int idx = tid + i * 256;
            int row = idx >> 3, c = idx & 7;
            int bloc = row >> 6, m = row & 63;
            int pc = c ^ (m & 7);
            cp16(bb + row * 128 + pc * 16,
                 Bh + ((size_t)(b0 + bloc) * NN + m0 + m) * CC + c * 8);
        }
        cp_commit();
    };

    int g = lid >> 3, lrw = lid & 7;
    int chHalf = g >> 1;
    uint32_t aBase = (uint32_t)(wm * 64 + (g & 1) * 8 + lrw) * 128;
    int bloc_w = wn >> 1;
    int warp_c = (wn & 1) * 32;
    uint32_t bRowRel = (uint32_t)(bloc_w * 64 + (g & 1) * 8 + lrw) * 128;
    int chunk0 = (warp_c >> 3) + chHalf;
    uint32_t bSw0 = (uint32_t)((chunk0 + 0) ^ lrw) * 16;
    uint32_t bSw1 = (uint32_t)((chunk0 + 2) ^ lrw) * 16;

    float acc[4][4][4];
#pragma unroll
    for (int mt = 0; mt < 4; mt++)
#pragma unroll
        for (int nt = 0; nt < 4; nt++)
#pragma unroll
            for (int q = 0; q < 4; q++) acc[mt][nt][q] = 0.f;

    load_tile(0, 0);
    load_tile(1, 1);

    const int ITERS = NN / 64;
    for (int it = 0; it < ITERS; it++) {
        int buf = it % 3;
        if (it == ITERS - 1) cp_wait0(); else cp_wait1();
        __syncthreads();
        uint32_t aB = sb + buf * 32768 + aBase;
        uint32_t bB = sb + buf * 32768 + 16384 + bRowRel;

#pragma unroll
        for (int ks = 0; ks < 4; ks++) {
            uint32_t af[4][4], bf[2][4];
            uint32_t apc = (uint32_t)((ks * 2 + chHalf) ^ lrw) * 16;
#pragma unroll
            for (int mt = 0; mt < 4; mt++) ldsm4(af[mt], aB + mt * 2048 + apc);
            uint32_t bko = (uint32_t)ks * 2048;
            ldsm4t(bf[0], bB + bko + bSw0);
            ldsm4t(bf[1], bB + bko + bSw1);
            if (ks == 0) {
                if (it + 2 < ITERS) load_tile(it + 2, (it + 2) % 3);
                else cp_commit();
            }
#pragma unroll
            for (int mt = 0; mt < 4; mt++) {
                mma16(acc[mt][0], af[mt], bf[0][0], bf[0][1]);
                mma16(acc[mt][1], af[mt], bf[0][2], bf[0][3]);
                mma16(acc[mt][2], af[mt], bf[1][0], bf[1][1]);
                mma16(acc[mt][3], af[mt], bf[1][2], bf[1][3]);
            }
        }
    }

    int lr = lid >> 2, lc = lid & 3;
#pragma unroll
    for (int mt = 0; mt < 4; mt++) {
#pragma unroll
        for (int nt = 0; nt < 4; nt++) {
            int n = n0 + wm * 64 + mt * 16 + lr;
            int bc = bc0 + wn * 32 + (nt >> 1) * 16 + (nt & 1) * 8 + lc * 2;
            int b = bc >> 6, c = bc & 63;
            float2 v0 = make_float2(acc[mt][nt][0], acc[mt][nt][1]);
            float2 v1 = make_float2(acc[mt][nt][2], acc[mt][nt][3]);
            if (mode == 2) {
                __half2 xh0 = *reinterpret_cast<const __half2*>(
                    Xh + ((size_t)b * NN + n) * CC + c);
                __half2 xh1 = *reinterpret_cast<const __half2*>(
                    Xh + ((size_t)b * NN + n + 8) * CC + c);
                float2 x0 = __half22float2(xh0);
                float2 x1 = __half22float2(xh1);
                v0.x = fmaf(2.f, v0.x, -x0.x);
                v0.y = fmaf(2.f, v0.y, -x0.y);
                v1.x = fmaf(2.f, v1.x, -x1.x);
                v1.y = fmaf(2.f, v1.y, -x1.y);
            }
            *reinterpret_cast<__half2*>(Yh + ((size_t)b * NN + n) * CC + c) =
                __floats2half2_rn(v0.x, v0.y);
            *reinterpret_cast<__half2*>(Yh + ((size_t)b * NN + n + 8) * CC + c) =
                __floats2half2_rn(v1.x, v1.y);
        }
    }
}

// ---------------------------------------------------------------------------
// out4: per-node fp16 tensor-core contraction. One block (128 thr, 4 warps) per n.
// ---------------------------------------------------------------------------
#define HSTR 200
#define OUT4_SMEM ((64 * HSTR * 2) * 2 + 64 * 4)
__global__ __launch_bounds__(128) void out4_kernel(const float* __restrict__ E,
                                                   const __half* __restrict__ WTg,
                                                   const float* __restrict__ bp,
                                                   float* __restrict__ OUT) {
    extern __shared__ char smc[];
    __half* XGs = reinterpret_cast<__half*>(smc);
    __half* WTs = XGs + 64 * HSTR;
    float* bs = reinterpret_cast<float*>(smc + 64 * HSTR * 2 * 2);
    __shared__ float en[EMBD];

    int n = blockIdx.x;
    int tid = threadIdx.x;
    int wid = tid >> 5;
    int lid = tid & 31;
    uint32_t xg_s = smem_u32(XGs);
    uint32_t wt_s = smem_u32(WTs);

    const __half* srcs[3] = {g_xh, g_y1h, g_y2h};
#pragma unroll
    for (int k = 0; k < 3; k++) {
        const __half* src = srcs[k];
#pragma unroll
        for (int rep = 0; rep < 4; rep++) {
            int c8 = tid + rep * 128;
            int b = c8 >> 3, i8 = c8 & 7;
            cp16(xg_s + (uint32_t)(b * HSTR + k * 64 + i8 * 8) * 2,
                 src + ((size_t)b * NN + n) * CC + i8 * 8);
        }
    }
    {
        const __half* src = WTg + (size_t)n * 12288;
#pragma unroll
        for (int rep = 0; rep < 12; rep++) {
            int c8 = tid + rep * 128;
            int idx = c8 * 8;
            int o = idx / 192, kk = idx - o * 192;
            cp16(wt_s + (uint32_t)(o * HSTR + kk) * 2, src + idx);
        }
    }
    cp_commit();

    if (tid < EMBD) en[tid] = E[n * EMBD + tid];
    __syncthreads();
    if (tid < 64) {
        float s = 0.f;
#pragma unroll
        for (int d = 0; d < EMBD; d++) s = fmaf(en[d], bp[d * 64 + tid], s);
        bs[tid] = s;
    }
    cp_wait0();
    __syncthreads();

    int lm = lid >> 3, lrw = lid & 7;
    uint32_t aLane = xg_s + (uint32_t)(wid * 16 + (lm & 1) * 8 + lrw) * (HSTR * 2) +
                     (lm >> 1) * 16;
    uint32_t bLane = wt_s + (uint32_t)((lm & 1) * 8 + lrw) * (HSTR * 2) +
                     (lm >> 1) * 16;

    float acc[8][4];
#pragma unroll
    for (int nt = 0; nt < 8; nt++)
#pragma unroll
        for (int q = 0; q < 4; q++) acc[nt][q] = 0.f;

#pragma unroll
    for (int kt = 0; kt < 12; kt++) {
        uint32_t koff = (uint32_t)kt * 32;
        uint32_t af[4];
        ldsm4(af, aLane + koff);
#pragma unroll
        for (int g = 0; g < 4; g++) {
            uint32_t bf[4];
            ldsm4(bf, bLane + g * 16 * (HSTR * 2) + koff);
            mma16(acc[g * 2 + 0], af, bf[0], bf[2]);
            mma16(acc[g * 2 + 1], af, bf[1], bf[3]);
        }
    }

    int lr = lid >> 2, lc = lid & 3;
    int b0 = wid * 16 + lr;
#pragma unroll
    for (int nt = 0; nt < 8; nt++) {
        int o = nt * 8 + lc * 2;
        float2 bias = *reinterpret_cast<const float2*>(&bs[o]);
        float2 v0 = make_float2(acc[nt][0] + bias.x, acc[nt][1] + bias.y);
        float2 v1 = make_float2(acc[nt][2] + bias.x, acc[nt][3] + bias.y);
        *reinterpret_cast<float2*>(OUT + ((size_t)b0 * NN + n) * CC + o) = v0;
        *reinterpret_cast<float2*>(OUT + ((size_t)(b0 + 8) * NN + n) * CC + o) = v1;
    }
}

// ---------------------------------------------------------------------------
extern "C" void kernel_launch(void* const* d_in, const int* in_sizes, int n_in,
                              void* d_out, int out_size) {
    const float *x = nullptr, *E = nullptr, *wp = nullptr, *bp = nullptr;
    for (int i = 0; i < n_in; i++) {
        switch (in_sizes[i]) {
            case BB * NN * CC:       x = (const float*)d_in[i]; break;
            case NN * EMBD:          E = (const float*)d_in[i]; break;
            case EMBD * 3 * CC * CC: wp = (const float*)d_in[i]; break;
            case EMBD * CC:          bp = (const float*)d_in[i]; break;
        }
    }
    float* out = (float*)d_out;

    __half *A, *xh, *y1h, *y2h, *WT;
    cudaGetSymbolAddress((void**)&A, g_A);
    cudaGetSymbolAddress((void**)&xh, g_xh);
    cudaGetSymbolAddress((void**)&y1h, g_y1h);
    cudaGetSymbolAddress((void**)&y2h, g_y2h);
    cudaGetSymbolAddress((void**)&WT, g_WT);

    // Stream-parallel DAG:
    //   main: supports -> gemm1 -> gemm2 -> out4
    //   sA:   xh        (joins before gemm1)
    //   sB:   wpre      (joins before out4 — overlaps both gemms)
    cudaStream_t sA, sB;
    cudaStreamCreateWithFlags(&sA, cudaStreamNonBlocking);
    cudaStreamCreateWithFlags(&sB, cudaStreamNonBlocking);
    cudaEvent_t eRoot, eA, eB;
    cudaEventCreateWithFlags(&eRoot, cudaEventDisableTiming);
    cudaEventCreateWithFlags(&eA, cudaEventDisableTiming);
    cudaEventCreateWithFlags(&eB, cudaEventDisableTiming);

    cudaEventRecord(eRoot, 0);
    cudaStreamWaitEvent(sA, eRoot, 0);
    cudaStreamWaitEvent(sB, eRoot, 0);

    int ssm = SR * NN * (int)sizeof(float);
    cudaFuncSetAttribute(supports_kernel, cudaFuncAttributeMaxDynamicSharedMemorySize, ssm);
    supports_kernel<<<NN / SR, 256, ssm, 0>>>(E, A);
    xh_kernel<<<(BB * NN * CC) / (256 * 16), 256, 0, sA>>>(x, xh);
    wpre_kernel<<<dim3(48, 64), 256, 0, sB>>>(E, wp, WT);

    cudaEventRecord(eA, sA);
    cudaStreamWaitEvent(0, eA, 0);

    cudaFuncSetAttribute(mma_gemm, cudaFuncAttributeMaxDynamicSharedMemorySize, GEMM_SMEM);
    dim3 ggrid(NN / 128, (BB * CC) / 128);
    mma_gemm<<<ggrid, 256, GEMM_SMEM, 0>>>(A, xh, y1h, nullptr, 1);
    mma_gemm<<<ggrid, 256, GEMM_SMEM, 0>>>(A, y1h, y2h, xh, 2);

    cudaEventRecord(eB, sB);
    cudaStreamWaitEvent(0, eB, 0);

    cudaFuncSetAttribute(out4_kernel, cudaFuncAttributeMaxDynamicSharedMemorySize, OUT4_SMEM);
    out4_kernel<<<NN, 128, OUT4_SMEM, 0>>>(E, WT, bp, out);

    cudaEventDestroy(eRoot);
    cudaEventDestroy(eA);
    cudaEventDestroy(eB);
    cudaStreamDestroy(sA);
    cudaStreamDestroy(sB);
}

// round 13
// speedup vs baseline: 1.1066x; 1.1000x over previous
#include <cuda_runtime.h>
#include <cuda_fp16.h>
#include <cstdint>

#define NN 2048
#define EMBD 16
#define BB 64
#define CC 64

// Scratch (no cudaMalloc allowed)
static __device__ __half g_A[NN * NN];            // adjacency, fp16
static __device__ __half g_xh[BB * NN * CC];      // fp16(x), [b][m][c]
static __device__ __half g_y1h[BB * NN * CC];     // A@X, fp16, [b][n][c]
static __device__ __half g_y2h[BB * NN * CC];     // 2A@y1 - X, fp16, [b][n][c]
static __device__ __half g_WT[NN * 3 * CC * CC];  // per-node weights [n][o][kk], fp16

// ---------------------------------------------------------------------------
__device__ __forceinline__ uint32_t smem_u32(const void* p) {
    uint32_t a;
    asm("{ .reg .u64 t; cvta.to.shared.u64 t, %1; cvt.u32.u64 %0, t; }" : "=r"(a) : "l"(p));
    return a;
}
__device__ __forceinline__ void cp16(uint32_t dst, const void* src) {
    asm volatile("cp.async.cg.shared.global [%0], [%1], 16;" :: "r"(dst), "l"(src));
}
__device__ __forceinline__ void cp_commit() { asm volatile("cp.async.commit_group;"); }
__device__ __forceinline__ void cp_wait1() { asm volatile("cp.async.wait_group 1;" ::: "memory"); }
__device__ __forceinline__ void cp_wait0() { asm volatile("cp.async.wait_group 0;" ::: "memory"); }

__device__ __forceinline__ void mma16(float* d, const uint32_t* a, uint32_t b0, uint32_t b1) {
    asm volatile(
        "mma.sync.aligned.m16n8k16.row.col.f32.f16.f16.f32 "
        "{%0,%1,%2,%3}, {%4,%5,%6,%7}, {%8,%9}, {%0,%1,%2,%3};"
        : "+f"(d[0]), "+f"(d[1]), "+f"(d[2]), "+f"(d[3])
        : "r"(a[0]), "r"(a[1]), "r"(a[2]), "r"(a[3]), "r"(b0), "r"(b1));
}
__device__ __forceinline__ void ldsm4(uint32_t* r, uint32_t addr) {
    asm volatile("ldmatrix.sync.aligned.m8n8.x4.shared.b16 {%0,%1,%2,%3}, [%4];"
                 : "=r"(r[0]), "=r"(r[1]), "=r"(r[2]), "=r"(r[3]) : "r"(addr));
}
__device__ __forceinline__ void ldsm4t(uint32_t* r, uint32_t addr) {
    asm volatile("ldmatrix.sync.aligned.m8n8.x4.trans.shared.b16 {%0,%1,%2,%3}, [%4];"
                 : "=r"(r[0]), "=r"(r[1]), "=r"(r[2]), "=r"(r[3]) : "r"(addr));
}

// ---------------------------------------------------------------------------
// K0: A[r,:] = fp16(softmax(relu(E[r] . E[j]))), 4 rows per block.
// ---------------------------------------------------------------------------
#define SR 4
__global__ __launch_bounds__(256) void supports_kernel(const float* __restrict__ E,
                                                       __half* __restrict__ A) {
    extern __shared__ float zs[];               // SR * NN
    __shared__ float red[SR][8];
    __shared__ float en[SR][EMBD];
    int row0 = blockIdx.x * SR;
    int tid = threadIdx.x;
    if (tid < SR * EMBD) en[tid >> 4][tid & 15] = E[row0 * EMBD + tid];
    __syncthreads();

    float er[SR][EMBD];
#pragma unroll
    for (int r = 0; r < SR; r++)
#pragma unroll
        for (int d = 0; d < EMBD; d++) er[r][d] = en[r][d];

    float lsum[SR] = {0.f, 0.f, 0.f, 0.f};
    for (int j = tid; j < NN; j += 256) {
        const float4* ej = reinterpret_cast<const float4*>(E + (size_t)j * EMBD);
        float4 v0 = ej[0], v1 = ej[1], v2 = ej[2], v3 = ej[3];
#pragma unroll
        for (int r = 0; r < SR; r++) {
            float s = 0.f;
            s = fmaf(er[r][0], v0.x, s);  s = fmaf(er[r][1], v0.y, s);
            s = fmaf(er[r][2], v0.z, s);  s = fmaf(er[r][3], v0.w, s);
            s = fmaf(er[r][4], v1.x, s);  s = fmaf(er[r][5], v1.y, s);
            s = fmaf(er[r][6], v1.z, s);  s = fmaf(er[r][7], v1.w, s);
            s = fmaf(er[r][8], v2.x, s);  s = fmaf(er[r][9], v2.y, s);
            s = fmaf(er[r][10], v2.z, s); s = fmaf(er[r][11], v2.w, s);
            s = fmaf(er[r][12], v3.x, s); s = fmaf(er[r][13], v3.y, s);
            s = fmaf(er[r][14], v3.z, s); s = fmaf(er[r][15], v3.w, s);
            float e = __expf(fmaxf(s, 0.f));
            zs[r * NN + j] = e;
            lsum[r] += e;
        }
    }
#pragma unroll
    for (int r = 0; r < SR; r++) {
#pragma unroll
        for (int o = 16; o > 0; o >>= 1) lsum[r] += __shfl_xor_sync(~0u, lsum[r], o);
        if ((tid & 31) == 0) red[r][tid >> 5] = lsum[r];
    }
    __syncthreads();
    float inv[SR];
#pragma unroll
    for (int r = 0; r < SR; r++) {
        float s = 0.f;
#pragma unroll
        for (int w = 0; w < 8; w++) s += red[r][w];
        inv[r] = 1.f / s;
    }
    for (int j = tid; j < NN; j += 256) {
#pragma unroll
        for (int r = 0; r < SR; r++)
            A[(size_t)(row0 + r) * NN + j] = __float2half_rn(zs[r * NN + j] * inv[r]);
    }
}

// ---------------------------------------------------------------------------
// xh: fp16 convert of x (same layout). 16 elems/thread.
// ---------------------------------------------------------------------------
__global__ __launch_bounds__(256) void xh_kernel(const float* __restrict__ X,
                                                 __half* __restrict__ D) {
    size_t base = ((size_t)blockIdx.x * 256 + threadIdx.x) * 16;
#pragma unroll
    for (int h = 0; h < 2; h++) {
        size_t i = base + h * 8;
        float4 a = *reinterpret_cast<const float4*>(X + i);
        float4 b = *reinterpret_cast<const float4*>(X + i + 4);
        union { uint4 u; __half2 hh[4]; } o;
        o.hh[0] = __floats2half2_rn(a.x, a.y);
        o.hh[1] = __floats2half2_rn(a.z, a.w);
        o.hh[2] = __floats2half2_rn(b.x, b.y);
        o.hh[3] = __floats2half2_rn(b.z, b.w);
        *reinterpret_cast<uint4*>(D + i) = o.u;
    }
}

// ---------------------------------------------------------------------------
// W precompute (transposed, fp16): WT[n][o*192 + kk] = fp16(sum_d E[n,d]*wp[d, kk*64+o])
// ---------------------------------------------------------------------------
__global__ __launch_bounds__(256) void wpre_kernel(const float* __restrict__ E,
                                                   const float* __restrict__ wp,
                                                   __half* __restrict__ WT) {
    __shared__ float wps[EMBD][256];
    __shared__ float Es[32][EMBD];
    int k0 = blockIdx.x * 4;
    int idx0 = blockIdx.x * 256;
    int n0 = blockIdx.y * 32;
    int tid = threadIdx.x;
#pragma unroll
    for (int i = 0; i < 4; i++) {
        int f = tid + i * 256;
        int d = f >> 6, c4 = f & 63;
        float4 v = *reinterpret_cast<const float4*>(wp + (size_t)d * 12288 + idx0 + c4 * 4);
        *reinterpret_cast<float4*>(&wps[d][c4 * 4]) = v;
    }
    if (tid < 128) {
        int nl = tid >> 2, dq = tid & 3;
        float4 v = *reinterpret_cast<const float4*>(E + (n0 + nl) * EMBD + dq * 4);
        *reinterpret_cast<float4*>(&Es[nl][dq * 4]) = v;
    }
    __syncthreads();

    int o = tid & 63;
    int g = tid >> 6;
    float wc[4][EMBD];
#pragma unroll
    for (int dk = 0; dk < 4; dk++)
#pragma unroll
        for (int d = 0; d < EMBD; d++) wc[dk][d] = wps[d][dk * 64 + o];

#pragma unroll
    for (int q = 0; q < 8; q++) {
        int nl = g * 8 + q;
        float s[4] = {0.f, 0.f, 0.f, 0.f};
#pragma unroll
        for (int d = 0; d < EMBD; d++) {
            float e = Es[nl][d];
#pragma unroll
            for (int dk = 0; dk < 4; dk++) s[dk] = fmaf(e, wc[dk][d], s[dk]);
        }
        __half2 h01 = __halves2half2(__float2half_rn(s[0]), __float2half_rn(s[1]));
        __half2 h23 = __halves2half2(__float2half_rn(s[2]), __float2half_rn(s[3]));
        __half2* dst = reinterpret_cast<__half2*>(
            WT + (size_t)(n0 + nl) * 12288 + o * 192 + k0);
        dst[0] = h01;
        dst[1] = h23;
    }
}

// ---------------------------------------------------------------------------
// fp16 mma.sync GEMM, B row-major via ldmatrix.trans, K=64 stages.
// CTA 128x128xK64, 8 warps (2m x 4n), warp tile 64x32, 3-stage cp.async.
// bc range offset by bc_off blocks (batch-chunk slicing for pipelining).
// mode 1: Yh = acc.  mode 2: Yh = 2*acc - Xh.
// ---------------------------------------------------------------------------
#define GEMM_SMEM 98304  // 3 stages x 32KB

__global__ __launch_bounds__(256, 2) void mma_gemm(const __half* __restrict__ Ag,
                                                   const __half* __restrict__ Bh,
                                                   __half* __restrict__ Yh,
                                                   const __half* __restrict__ Xh,
                                                   int mode, int bc_off) {
    extern __shared__ char smc[];
    uint32_t sb = smem_u32(smc);

    int tid = threadIdx.x;
    int wid = tid >> 5;
    int lid = tid & 31;
    int wm = wid & 1;
    int wn = wid >> 1;
    int n0 = blockIdx.x * 128;
    int bc0 = (blockIdx.y + bc_off) * 128;
    int b0 = bc0 >> 6;

    const __half* Arow = Ag + (size_t)n0 * NN;

    auto load_tile = [&](int it, int buf) {
        int m0 = it * 64;
        uint32_t ab = sb + buf * 32768;
        uint32_t bb = ab + 16384;
#pragma unroll
        for (int i = 0; i < 4; i++) {
            int idx = tid + i * 256;
            int row = idx >> 3, c = idx & 7;
            int pc = c ^ (row & 7);
            cp16(ab + row * 128 + pc * 16, Arow + (size_t)row * NN + m0 + c * 8);
        }
#pragma unroll
        for (int i = 0; i < 4; i++) {
            int idx = tid + i * 256;
            int row = idx >> 3, c = idx & 7;
            int bloc = row >> 6, m = row & 63;
            int pc = c ^ (m & 7);
            cp16(bb + row * 128 + pc * 16,
                 Bh + ((size_t)(b0 + bloc) * NN + m0 + m) * CC + c * 8);
        }
        cp_commit();
    };

    int g = lid >> 3, lrw = lid & 7;
    int chHalf = g >> 1;
    uint32_t aBase = (uint32_t)(wm * 64 + (g & 1) * 8 + lrw) * 128;
    int bloc_w = wn >> 1;
    int warp_c = (wn & 1) * 32;
    uint32_t bRowRel = (uint32_t)(bloc_w * 64 + (g & 1) * 8 + lrw) * 128;
    int chunk0 = (warp_c >> 3) + chHalf;
    uint32_t bSw0 = (uint32_t)((chunk0 + 0) ^ lrw) * 16;
    uint32_t bSw1 = (uint32_t)((chunk0 + 2) ^ lrw) * 16;

    float acc[4][4][4];
#pragma unroll
    for (int mt = 0; mt < 4; mt++)
#pragma unroll
        for (int nt = 0; nt < 4; nt++)
#pragma unroll
            for (int q = 0; q < 4; q++) acc[mt][nt][q] = 0.f;

    load_tile(0, 0);
    load_tile(1, 1);

    const int ITERS = NN / 64;
    for (int it = 0; it < ITERS; it++) {
        int buf = it % 3;
        if (it == ITERS - 1) cp_wait0(); else cp_wait1();
        __syncthreads();
        uint32_t aB = sb + buf * 32768 + aBase;
        uint32_t bB = sb + buf * 32768 + 16384 + bRowRel;

#pragma unroll
        for (int ks = 0; ks < 4; ks++) {
            uint32_t af[4][4], bf[2][4];
            uint32_t apc = (uint32_t)((ks * 2 + chHalf) ^ lrw) * 16;
#pragma unroll
            for (int mt = 0; mt < 4; mt++) ldsm4(af[mt], aB + mt * 2048 + apc);
            uint32_t bko = (uint32_t)ks * 2048;
            ldsm4t(bf[0], bB + bko + bSw0);
            ldsm4t(bf[1], bB + bko + bSw1);
            if (ks == 0) {
                if (it + 2 < ITERS) load_tile(it + 2, (it + 2) % 3);
                else cp_commit();
            }
#pragma unroll
            for (int mt = 0; mt < 4; mt++) {
                mma16(acc[mt][0], af[mt], bf[0][0], bf[0][1]);
                mma16(acc[mt][1], af[mt], bf[0][2], bf[0][3]);
                mma16(acc[mt][2], af[mt], bf[1][0], bf[1][1]);
                mma16(acc[mt][3], af[mt], bf[1][2], bf[1][3]);
            }
        }
    }

    int lr = lid >> 2, lc = lid & 3;
#pragma unroll
    for (int mt = 0; mt < 4; mt++) {
#pragma unroll
        for (int nt = 0; nt < 4; nt++) {
            int n = n0 + wm * 64 + mt * 16 + lr;
            int bc = bc0 + wn * 32 + (nt >> 1) * 16 + (nt & 1) * 8 + lc * 2;
            int b = bc >> 6, c = bc & 63;
            float2 v0 = make_float2(acc[mt][nt][0], acc[mt][nt][1]);
            float2 v1 = make_float2(acc[mt][nt][2], acc[mt][nt][3]);
            if (mode == 2) {
                __half2 xh0 = *reinterpret_cast<const __half2*>(
                    Xh + ((size_t)b * NN + n) * CC + c);
                __half2 xh1 = *reinterpret_cast<const __half2*>(
                    Xh + ((size_t)b * NN + n + 8) * CC + c);
                float2 x0 = __half22float2(xh0);
                float2 x1 = __half22float2(xh1);
                v0.x = fmaf(2.f, v0.x, -x0.x);
                v0.y = fmaf(2.f, v0.y, -x0.y);
                v1.x = fmaf(2.f, v1.x, -x1.x);
                v1.y = fmaf(2.f, v1.y, -x1.y);
            }
            *reinterpret_cast<__half2*>(Yh + ((size_t)b * NN + n) * CC + c) =
                __floats2half2_rn(v0.x, v0.y);
            *reinterpret_cast<__half2*>(Yh + ((size_t)b * NN + n + 8) * CC + c) =
                __floats2half2_rn(v1.x, v1.y);
        }
    }
}

// ---------------------------------------------------------------------------
// out4: per-node fp16 tensor-core contraction. One block (128 thr, 4 warps) per n.
// ---------------------------------------------------------------------------
#define HSTR 200
#define OUT4_SMEM ((64 * HSTR * 2) * 2 + 64 * 4)
__global__ __launch_bounds__(128) void out4_kernel(const float* __restrict__ E,
                                                   const __half* __restrict__ WTg,
                                                   const float* __restrict__ bp,
                                                   float* __restrict__ OUT) {
    extern __shared__ char smc[];
    __half* XGs = reinterpret_cast<__half*>(smc);
    __half* WTs = XGs + 64 * HSTR;
    float* bs = reinterpret_cast<float*>(smc + 64 * HSTR * 2 * 2);
    __shared__ float en[EMBD];

    int n = blockIdx.x;
    int tid = threadIdx.x;
    int wid = tid >> 5;
    int lid = tid & 31;
    uint32_t xg_s = smem_u32(XGs);
    uint32_t wt_s = smem_u32(WTs);

    const __half* srcs[3] = {g_xh, g_y1h, g_y2h};
#pragma unroll
    for (int k = 0; k < 3; k++) {
        const __half* src = srcs[k];
#pragma unroll
        for (int rep = 0; rep < 4; rep++) {
            int c8 = tid + rep * 128;
            int b = c8 >> 3, i8 = c8 & 7;
            cp16(xg_s + (uint32_t)(b * HSTR + k * 64 + i8 * 8) * 2,
                 src + ((size_t)b * NN + n) * CC + i8 * 8);
        }
    }
    {
        const __half* src = WTg + (size_t)n * 12288;
#pragma unroll
        for (int rep = 0; rep < 12; rep++) {
            int c8 = tid + rep * 128;
            int idx = c8 * 8;
            int o = idx / 192, kk = idx - o * 192;
            cp16(wt_s + (uint32_t)(o * HSTR + kk) * 2, src + idx);
        }
    }
    cp_commit();

    if (tid < EMBD) en[tid] = E[n * EMBD + tid];
    __syncthreads();
    if (tid < 64) {
        float s = 0.f;
#pragma unroll
        for (int d = 0; d < EMBD; d++) s = fmaf(en[d], bp[d * 64 + tid], s);
        bs[tid] = s;
    }
    cp_wait0();
    __syncthreads();

    int lm = lid >> 3, lrw = lid & 7;
    uint32_t aLane = xg_s + (uint32_t)(wid * 16 + (lm & 1) * 8 + lrw) * (HSTR * 2) +
                     (lm >> 1) * 16;
    uint32_t bLane = wt_s + (uint32_t)((lm & 1) * 8 + lrw) * (HSTR * 2) +
                     (lm >> 1) * 16;

    float acc[8][4];
#pragma unroll
    for (int nt = 0; nt < 8; nt++)
#pragma unroll
        for (int q = 0; q < 4; q++) acc[nt][q] = 0.f;

#pragma unroll
    for (int kt = 0; kt < 12; kt++) {
        uint32_t koff = (uint32_t)kt * 32;
        uint32_t af[4];
        ldsm4(af, aLane + koff);
#pragma unroll
        for (int g = 0; g < 4; g++) {
            uint32_t bf[4];
            ldsm4(bf, bLane + g * 16 * (HSTR * 2) + koff);
            mma16(acc[g * 2 + 0], af, bf[0], bf[2]);
            mma16(acc[g * 2 + 1], af, bf[1], bf[3]);
        }
    }

    int lr = lid >> 2, lc = lid & 3;
    int b0 = wid * 16 + lr;
#pragma unroll
    for (int nt = 0; nt < 8; nt++) {
        int o = nt * 8 + lc * 2;
        float2 bias = *reinterpret_cast<const float2*>(&bs[o]);
        float2 v0 = make_float2(acc[nt][0] + bias.x, acc[nt][1] + bias.y);
        float2 v1 = make_float2(acc[nt][2] + bias.x, acc[nt][3] + bias.y);
        *reinterpret_cast<float2*>(OUT + ((size_t)b0 * NN + n) * CC + o) = v0;
        *reinterpret_cast<float2*>(OUT + ((size_t)(b0 + 8) * NN + n) * CC + o) = v1;
    }
}

// ---------------------------------------------------------------------------
extern "C" void kernel_launch(void* const* d_in, const int* in_sizes, int n_in,
                              void* d_out, int out_size) {
    const float *x = nullptr, *E = nullptr, *wp = nullptr, *bp = nullptr;
    for (int i = 0; i < n_in; i++) {
        switch (in_sizes[i]) {
            case BB * NN * CC:       x = (const float*)d_in[i]; break;
            case NN * EMBD:          E = (const float*)d_in[i]; break;
            case EMBD * 3 * CC * CC: wp = (const float*)d_in[i]; break;
            case EMBD * CC:          bp = (const float*)d_in[i]; break;
        }
    }
    float* out = (float*)d_out;

    __half *A, *xh, *y1h, *y2h, *WT;
    cudaGetSymbolAddress((void**)&A, g_A);
    cudaGetSymbolAddress((void**)&xh, g_xh);
    cudaGetSymbolAddress((void**)&y1h, g_y1h);
    cudaGetSymbolAddress((void**)&y2h, g_y2h);
    cudaGetSymbolAddress((void**)&WT, g_WT);

    // DAG: supports,xh gate 4 parallel gemm chains [g1_i -> g2_i] (16 b each);
    // wpre runs on its own stream, joining (with all chains) before out4.
    cudaStream_t sA, sB, sC, sD;
    cudaStreamCreateWithFlags(&sA, cudaStreamNonBlocking);
    cudaStreamCreateWithFlags(&sB, cudaStreamNonBlocking);
    cudaStreamCreateWithFlags(&sC, cudaStreamNonBlocking);
    cudaStreamCreateWithFlags(&sD, cudaStreamNonBlocking);
    cudaEvent_t eRoot, eS, eX, e1, e2, e3, eW;
    cudaEventCreateWithFlags(&eRoot, cudaEventDisableTiming);
    cudaEventCreateWithFlags(&eS, cudaEventDisableTiming);
    cudaEventCreateWithFlags(&eX, cudaEventDisableTiming);
    cudaEventCreateWithFlags(&e1, cudaEventDisableTiming);
    cudaEventCreateWithFlags(&e2, cudaEventDisableTiming);
    cudaEventCreateWithFlags(&e3, cudaEventDisableTiming);
    cudaEventCreateWithFlags(&eW, cudaEventDisableTiming);

    cudaEventRecord(eRoot, 0);
    cudaStreamWaitEvent(sA, eRoot, 0);
    cudaStreamWaitEvent(sB, eRoot, 0);
    cudaStreamWaitEvent(sC, eRoot, 0);
    cudaStreamWaitEvent(sD, eRoot, 0);

    int ssm = SR * NN * (int)sizeof(float);
    cudaFuncSetAttribute(supports_kernel, cudaFuncAttributeMaxDynamicSharedMemorySize, ssm);
    supports_kernel<<<NN / SR, 256, ssm, 0>>>(E, A);
    cudaEventRecord(eS, 0);
    xh_kernel<<<(BB * NN * CC) / (256 * 16), 256, 0, sA>>>(x, xh);
    cudaEventRecord(eX, sA);
    wpre_kernel<<<dim3(48, 64), 256, 0, sD>>>(E, wp, WT);
    cudaEventRecord(eW, sD);

    cudaFuncSetAttribute(mma_gemm, cudaFuncAttributeMaxDynamicSharedMemorySize, GEMM_SMEM);
    dim3 qgrid(NN / 128, 8);   // 16 x 8 = 128 CTAs per quarter (16 b)

    // chain 0 on stream 0 (has supports; wait xh)
    cudaStreamWaitEvent(0, eX, 0);
    mma_gemm<<<qgrid, 256, GEMM_SMEM, 0>>>(A, xh, y1h, nullptr, 1, 0);
    mma_gemm<<<qgrid, 256, GEMM_SMEM, 0>>>(A, y1h, y2h, xh, 2, 0);

    // chain 1 on sA (has xh; wait supports)
    cudaStreamWaitEvent(sA, eS, 0);
    mma_gemm<<<qgrid, 256, GEMM_SMEM, sA>>>(A, xh, y1h, nullptr, 1, 8);
    mma_gemm<<<qgrid, 256, GEMM_SMEM, sA>>>(A, y1h, y2h, xh, 2, 8);
    cudaEventRecord(e1, sA);

    // chain 2 on sB (wait supports + xh)
    cudaStreamWaitEvent(sB, eS, 0);
    cudaStreamWaitEvent(sB, eX, 0);
    mma_gemm<<<qgrid, 256, GEMM_SMEM, sB>>>(A, xh, y1h, nullptr, 1, 16);
    mma_gemm<<<qgrid, 256, GEMM_SMEM, sB>>>(A, y1h, y2h, xh, 2, 16);
    cudaEventRecord(e2, sB);

    // chain 3 on sC (wait supports + xh)
    cudaStreamWaitEvent(sC, eS, 0);
    cudaStreamWaitEvent(sC, eX, 0);
    mma_gemm<<<qgrid, 256, GEMM_SMEM, sC>>>(A, xh, y1h, nullptr, 1, 24);
    mma_gemm<<<qgrid, 256, GEMM_SMEM, sC>>>(A, y1h, y2h, xh, 2, 24);
    cudaEventRecord(e3, sC);

    // out4 on stream 0 after all chains + wpre
    cudaStreamWaitEvent(0, e1, 0);
    cudaStreamWaitEvent(0, e2, 0);
    cudaStreamWaitEvent(0, e3, 0);
    cudaStreamWaitEvent(0, eW, 0);
    cudaFuncSetAttribute(out4_kernel, cudaFuncAttributeMaxDynamicSharedMemorySize, OUT4_SMEM);
    out4_kernel<<<NN, 128, OUT4_SMEM, 0>>>(E, WT, bp, out);

    cudaEventDestroy(eRoot);
    cudaEventDestroy(eS);
    cudaEventDestroy(eX);
    cudaEventDestroy(e1);
    cudaEventDestroy(e2);
    cudaEventDestroy(e3);
    cudaEventDestroy(eW);
    cudaStreamDestroy(sA);
    cudaStreamDestroy(sB);
    cudaStreamDestroy(sC);
    cudaStreamDestroy(sD);
}